// round 3
// baseline (speedup 1.0000x reference)
#include <cuda_runtime.h>

// EWMA over axis 0 of x[4096][64][256] fp32.
// y[0] = x[0]; y[t] = 0.3*x[t] + 0.7*y[t-1]
//
// Chunk-parallel scan: 0.7^24 ~ 1.9e-4 worst-case (measured ~5x lower), so
// each time-chunk reconstructs its starting state from 24 warmup steps of
// raw x. CHUNK=64 -> 64 chunks -> 8192 warps for TLP; 64-reg budget lets
// ptxas batch independent float4 loads ahead of the FMA chain for ILP.

static constexpr int T      = 4096;
static constexpr int C      = 64 * 256;      // 16384 channels
static constexpr int C4     = C / 4;         // 4096 float4 groups per timestep
static constexpr int CHUNK  = 64;            // timesteps per chunk
static constexpr int NCHUNK = T / CHUNK;     // 64
static constexpr int WARM   = 24;            // 0.7^24 ~ 1.9e-4

static constexpr float ALPHA = 0.3f;
static constexpr float BETA  = 0.7f;

__global__ __launch_bounds__(128, 8)
void ewma_kernel(const float4* __restrict__ x, float4* __restrict__ y)
{
    const int group = blockIdx.x * blockDim.x + threadIdx.x;  // [0, C4)
    const int chunk = blockIdx.y;                              // [0, NCHUNK)

    const int t0 = chunk * CHUNK;

    float4 acc;
    int t;

    if (chunk == 0) {
        // Exact start: y[0] = x[0]
        acc = __ldcs(&x[(size_t)0 * C4 + group]);
        __stcs(&y[group], acc);
        t = 1;
    } else {
        // Warmup: seed from raw x at t0-WARM, run WARM recurrence steps.
        const int tw = t0 - WARM;
        acc = __ldcs(&x[(size_t)tw * C4 + group]);
        #pragma unroll 8
        for (int ti = tw + 1; ti < t0; ++ti) {
            float4 v = __ldcs(&x[(size_t)ti * C4 + group]);
            acc.x = fmaf(BETA, acc.x, ALPHA * v.x);
            acc.y = fmaf(BETA, acc.y, ALPHA * v.y);
            acc.z = fmaf(BETA, acc.z, ALPHA * v.z);
            acc.w = fmaf(BETA, acc.w, ALPHA * v.w);
        }
        t = t0;
    }

    const int tend = t0 + CHUNK;
    #pragma unroll 8
    for (; t < tend; ++t) {
        float4 v = __ldcs(&x[(size_t)t * C4 + group]);
        acc.x = fmaf(BETA, acc.x, ALPHA * v.x);
        acc.y = fmaf(BETA, acc.y, ALPHA * v.y);
        acc.z = fmaf(BETA, acc.z, ALPHA * v.z);
        acc.w = fmaf(BETA, acc.w, ALPHA * v.w);
        __stcs(&y[(size_t)t * C4 + group], acc);
    }
}

extern "C" void kernel_launch(void* const* d_in, const int* in_sizes, int n_in,
                              void* d_out, int out_size)
{
    const float4* x = (const float4*)d_in[0];
    float4*       y = (float4*)d_out;

    dim3 block(128);
    dim3 grid(C4 / 128, NCHUNK);   // (32, 64) -> 2048 CTAs, 8192 warps
    ewma_kernel<<<grid, block>>>(x, y);
}

// round 4
// speedup vs baseline: 1.0884x; 1.0884x over previous
#include <cuda_runtime.h>

// EWMA over axis 0 of x[4096][64][256] fp32.
// y[0] = x[0]; y[t] = 0.3*x[t] + 0.7*y[t-1]
//
// Chunk-parallel scan. Measured error law: rel_err ~= 0.32 * 0.7^WARM, so
// WARM=22 -> ~1.3e-4 (8x under the 1e-3 gate). Chunk k's warmup rows are
// chunk k-1's last main rows: grid is ordered chunk-fastest and reads use
// __ldcg so the second toucher hits L2 instead of DRAM.

static constexpr int T      = 4096;
static constexpr int C      = 64 * 256;      // 16384 channels
static constexpr int C4     = C / 4;         // 4096 float4 groups per timestep
static constexpr int CHUNK  = 128;           // timesteps per chunk
static constexpr int NCHUNK = T / CHUNK;     // 32
static constexpr int WARM   = 22;            // 0.32*0.7^22 ~ 1.3e-4

static constexpr float ALPHA = 0.3f;
static constexpr float BETA  = 0.7f;

__global__ __launch_bounds__(128, 8)
void ewma_kernel(const float4* __restrict__ x, float4* __restrict__ y)
{
    // chunk varies fastest across CTAs -> adjacent chunks co-resident,
    // maximizing L2 overlap between chunk k warmup and chunk k-1 mainloop.
    const int chunk = blockIdx.x;                              // [0, NCHUNK)
    const int group = blockIdx.y * blockDim.x + threadIdx.x;   // [0, C4)

    const int t0 = chunk * CHUNK;

    float4 acc;
    int t;

    if (chunk == 0) {
        // Exact start: y[0] = x[0]
        acc = __ldcg(&x[(size_t)0 * C4 + group]);
        __stcs(&y[group], acc);
        t = 1;
    } else {
        // Warmup: seed from raw x at t0-WARM, run WARM recurrence steps.
        const int tw = t0 - WARM;
        acc = __ldcg(&x[(size_t)tw * C4 + group]);
        #pragma unroll 8
        for (int ti = tw + 1; ti < t0; ++ti) {
            float4 v = __ldcg(&x[(size_t)ti * C4 + group]);
            acc.x = fmaf(BETA, acc.x, ALPHA * v.x);
            acc.y = fmaf(BETA, acc.y, ALPHA * v.y);
            acc.z = fmaf(BETA, acc.z, ALPHA * v.z);
            acc.w = fmaf(BETA, acc.w, ALPHA * v.w);
        }
        t = t0;
    }

    const int tend = t0 + CHUNK;
    #pragma unroll 8
    for (; t < tend; ++t) {
        float4 v = __ldcg(&x[(size_t)t * C4 + group]);
        acc.x = fmaf(BETA, acc.x, ALPHA * v.x);
        acc.y = fmaf(BETA, acc.y, ALPHA * v.y);
        acc.z = fmaf(BETA, acc.z, ALPHA * v.z);
        acc.w = fmaf(BETA, acc.w, ALPHA * v.w);
        __stcs(&y[(size_t)t * C4 + group], acc);
    }
}

extern "C" void kernel_launch(void* const* d_in, const int* in_sizes, int n_in,
                              void* d_out, int out_size)
{
    const float4* x = (const float4*)d_in[0];
    float4*       y = (float4*)d_out;

    dim3 block(128);
    dim3 grid(NCHUNK, C4 / 128);   // (32, 32) -> 1024 CTAs, chunk fastest
    ewma_kernel<<<grid, block>>>(x, y);
}